// round 14
// baseline (speedup 1.0000x reference)
#include <cuda_runtime.h>
#include <math.h>
#include <stdint.h>

#define NB 32
#define NS 8192
#define ND 256
#define NCHUNK 32          // blocks per batch in main pass
#define POS_PER_BLOCK 256  // rows per block
#define TILE_ROWS 16       // rows per cp.async tile
#define NTILES (POS_PER_BLOCK / TILE_ROWS)   // 16
#define NSTAGE 4
#define TILE_BYTES (TILE_ROWS * ND * 4)      // 16384
#define NPRE 16            // k_pre reduction split
#define EXP_OFF 48.0f      // fixed softmax offset (energies << 48+88)

// ---------------- scratch (no allocation allowed) ----------------
__device__ float g_Vp[NB * NPRE * ND];     // partial v[b] (k_pre out)
__device__ float g_V[NB * ND];             // final v[b]   (k_pre2 out)
__device__ float g_c0[NB];                 // ht[b] . Wa_b
__device__ float g_PL[NB * NCHUNK];        // per-block partial sum (fixed offset)
__device__ float g_PA[NB * NCHUNK * ND];   // per-block partial weighted row-sum

// ---------------- cp.async helpers ----------------
__device__ __forceinline__ void cp16(uint32_t dst, const void* src) {
    asm volatile("cp.async.cg.shared.global [%0], [%1], 16;\n" :: "r"(dst), "l"(src));
}
__device__ __forceinline__ void cp_commit() {
    asm volatile("cp.async.commit_group;\n" ::: "memory");
}
template <int N>
__device__ __forceinline__ void cp_wait() {
    asm volatile("cp.async.wait_group %0;\n" :: "n"(N) : "memory");
}

// ---------------- K1: partial v[b], c0[b] (16-way split over d) ----------
__global__ void __launch_bounds__(256)
k_pre(const float* __restrict__ ht,
      const float* __restrict__ Wa_w,
      const float* __restrict__ Wa_b) {
    int g = blockIdx.x, b = blockIdx.y, t = threadIdx.x;
    __shared__ float sh[16];
    if (t < 16) sh[t] = ht[b * ND + g * 16 + t];
    __syncthreads();
    const float* Wp = Wa_w + (size_t)(g * 16) * ND + t;
    float acc = 0.f;
    #pragma unroll
    for (int d = 0; d < 16; d++)                      // 16 loads, all in flight
        acc = fmaf(sh[d], Wp[(size_t)d * ND], acc);
    g_Vp[(b * NPRE + g) * ND + t] = acc;

    if (g == 0) {   // c0 = ht . Wa_b
        __shared__ float red[ND];
        red[t] = ht[b * ND + t] * Wa_b[t];
        __syncthreads();
        for (int s = 128; s > 0; s >>= 1) {
            if (t < s) red[t] += red[t + s];
            __syncthreads();
        }
        if (t == 0) g_c0[b] = red[0];
    }
}

// ---------------- K1b: fold 16 partials -> g_V (L2-hot, tiny) ------------
__global__ void __launch_bounds__(256)
k_pre2() {
    int b = blockIdx.x, t = threadIdx.x;
    const float* p = g_Vp + (size_t)b * NPRE * ND + t;
    float a0 = 0.f, a1 = 0.f, a2 = 0.f, a3 = 0.f;
    #pragma unroll
    for (int g = 0; g < NPRE; g += 4) {               // 16 loads in flight
        a0 += p[(g + 0) * ND];
        a1 += p[(g + 1) * ND];
        a2 += p[(g + 2) * ND];
        a3 += p[(g + 3) * ND];
    }
    g_V[b * ND + t] = (a0 + a1) + (a2 + a3);
}

// ---------------- K2: 4-buffer cp.async pipeline, 2 tiles in flight ------
// Invariant per iteration t: issue tile t+2 into slot (t+2)&3, then wait so
// tile t is resident, one barrier, compute slot t&3. Slot (t+2)&3 was last
// READ at iteration t-2, and every thread passed the t-1 barrier after that
// read, so the issue is race-free with a single barrier per tile.
__global__ void __launch_bounds__(256, 3)
k_main(const float* __restrict__ hs, const int* __restrict__ slen,
       float* __restrict__ alpha) {
    __shared__ __align__(16) float sbuf[NSTAGE][TILE_ROWS * ND];  // 64KB

    int chunk = blockIdx.x, b = blockIdx.y;
    int tid = threadIdx.x, w = tid >> 5, lane = tid & 31;
    int len = slen[b];
    int len_eff = (len == 0) ? NS : len;
    float off = (len == 0) ? -10000.f : EXP_OFF;

    if (chunk * POS_PER_BLOCK >= len_eff) return;

    const float* gsrc = hs + ((size_t)b * NS + chunk * POS_PER_BLOCK) * ND;
    uint32_t sb = (uint32_t)__cvta_generic_to_shared(&sbuf[0][0]);

    // stage tiles 0 and 1
    #pragma unroll
    for (int tt = 0; tt < 2; tt++) {
        uint32_t dst = sb + tt * TILE_BYTES;
        const char* src = (const char*)(gsrc + tt * TILE_ROWS * ND);
        #pragma unroll
        for (int k = 0; k < 4; k++)
            cp16(dst + (tid + k * 256) * 16, src + (size_t)(tid + k * 256) * 16);
        cp_commit();
    }

    // v fragments: 2 loads from final g_V (L2-hot)
    float c0 = g_c0[b];
    const float4* v4 = (const float4*)(g_V + b * ND);
    float4 va = v4[lane], vb = v4[lane + 32];

    float Lsum = 0.f;
    float4 Aa = make_float4(0.f, 0.f, 0.f, 0.f);
    float4 Ab = make_float4(0.f, 0.f, 0.f, 0.f);
    int s0 = chunk * POS_PER_BLOCK;

    #pragma unroll 1
    for (int t = 0; t < NTILES; t++) {
        if (t + 2 < NTILES) {            // issue tile t+2 (2 in flight)
            uint32_t dst = sb + ((t + 2) & 3) * TILE_BYTES;
            const char* src = (const char*)(gsrc + (t + 2) * TILE_ROWS * ND);
            #pragma unroll
            for (int k = 0; k < 4; k++)
                cp16(dst + (tid + k * 256) * 16, src + (size_t)(tid + k * 256) * 16);
            cp_commit();
        }
        if (t < NTILES - 2)      cp_wait<2>();
        else if (t < NTILES - 1) cp_wait<1>();
        else                     cp_wait<0>();
        __syncthreads();                 // single barrier per tile

        // compute: warp w handles rows 2w, 2w+1 of tile t (slot t&3)
        const float* sp = sbuf[t & 3] + (2 * w) * ND;
        float4 r1a = ((const float4*)sp)[lane];
        float4 r1b = ((const float4*)sp)[lane + 32];
        float4 r2a = ((const float4*)sp)[64 + lane];
        float4 r2b = ((const float4*)sp)[64 + lane + 32];

        float p1 = r1a.x*va.x + r1a.y*va.y + r1a.z*va.z + r1a.w*va.w
                 + r1b.x*vb.x + r1b.y*vb.y + r1b.z*vb.z + r1b.w*vb.w;
        float p2 = r2a.x*va.x + r2a.y*va.y + r2a.z*va.z + r2a.w*va.w
                 + r2b.x*vb.x + r2b.y*vb.y + r2b.z*vb.z + r2b.w*vb.w;
        #pragma unroll
        for (int o = 16; o > 0; o >>= 1) {
            p1 += __shfl_xor_sync(0xffffffffu, p1, o);
            p2 += __shfl_xor_sync(0xffffffffu, p2, o);
        }
        int s = s0 + t * TILE_ROWS + 2 * w;
        float e1 = p1 + c0, e2 = p2 + c0;
        e1 = (e1 > 0.f) ? e1 : 0.2f * e1;            // leaky relu
        e2 = (e2 > 0.f) ? e2 : 0.2f * e2;
        if (s + 0 >= len) e1 = -10000.f;             // length mask
        if (s + 1 >= len) e2 = -10000.f;
        if (lane == 0)
            *(float2*)(alpha + (size_t)b * NS + s) = make_float2(e1, e2);

        float q1 = __expf(e1 - off);                 // fixed offset softmax
        float q2 = __expf(e2 - off);
        Lsum += q1 + q2;
        Aa.x = fmaf(q2, r2a.x, fmaf(q1, r1a.x, Aa.x));
        Aa.y = fmaf(q2, r2a.y, fmaf(q1, r1a.y, Aa.y));
        Aa.z = fmaf(q2, r2a.z, fmaf(q1, r1a.z, Aa.z));
        Aa.w = fmaf(q2, r2a.w, fmaf(q1, r1a.w, Aa.w));
        Ab.x = fmaf(q2, r2b.x, fmaf(q1, r1b.x, Ab.x));
        Ab.y = fmaf(q2, r2b.y, fmaf(q1, r1b.y, Ab.y));
        Ab.z = fmaf(q2, r2b.z, fmaf(q1, r1b.z, Ab.z));
        Ab.w = fmaf(q2, r2b.w, fmaf(q1, r1b.w, Ab.w));
    }

    // combine 8 warps (sA/sL overlaid onto sbuf[0]; all tile reads complete:
    // slot 0 last read at t=12, every thread passed the t=13.. barriers)
    float* sA  = &sbuf[0][0];        // 8 x 256
    float* sLp = sA + 8 * ND;        // 8 floats (buffer holds 4096 floats)
    float* arow = sA + w * ND;
    arow[lane * 4 + 0] = Aa.x; arow[lane * 4 + 1] = Aa.y;
    arow[lane * 4 + 2] = Aa.z; arow[lane * 4 + 3] = Aa.w;
    arow[128 + lane * 4 + 0] = Ab.x; arow[128 + lane * 4 + 1] = Ab.y;
    arow[128 + lane * 4 + 2] = Ab.z; arow[128 + lane * 4 + 3] = Ab.w;
    if (lane == 0) sLp[w] = Lsum;
    __syncthreads();

    float acc = 0.f;
    #pragma unroll
    for (int j = 0; j < 8; j++) acc += sA[j * ND + tid];
    int pid = b * NCHUNK + chunk;
    g_PA[pid * ND + tid] = acc;
    if (tid == 0) {
        float lb = 0.f;
        #pragma unroll
        for (int j = 0; j < 8; j++) lb += sLp[j];
        g_PL[pid] = lb;
    }
}

// ---------------- K3: combine + context GEMV + alpha normalize (R11) -----
__global__ void __launch_bounds__(256)
k_fin(const float* __restrict__ Wc_w, const float* __restrict__ Wc_b,
      const int* __restrict__ slen, float* __restrict__ alpha,
      float* __restrict__ out_ctx) {
    int b = blockIdx.x, t = threadIdx.x, w = t >> 5, lane = t & 31;
    int len = slen[b];
    int len_eff = (len == 0) ? NS : len;
    float off = (len == 0) ? -10000.f : EXP_OFF;
    int nval = (len_eff + POS_PER_BLOCK - 1) / POS_PER_BLOCK;

    __shared__ float sLs[NCHUNK];
    __shared__ __align__(16) float sm[ND];
    if (t < NCHUNK) sLs[t] = (t < nval) ? g_PL[b * NCHUNK + t] : 0.f;
    __syncthreads();
    float Lg = 0.f;
    #pragma unroll 8
    for (int j = 0; j < NCHUNK; j++) Lg += sLs[j];
    float m = 0.f;
    #pragma unroll 8
    for (int j = 0; j < nval; j++)
        m += g_PA[(b * NCHUNK + j) * ND + t];
    float Rinv = 1.f / Lg;
    m *= Rinv;
    sm[t] = m;
    __syncthreads();

    // context GEMV: warp per output row
    const float4* m4 = (const float4*)sm;
    float4 ma = m4[lane], mb = m4[lane + 32];
    #pragma unroll
    for (int d = w; d < ND; d += 8) {
        const float4* wr = (const float4*)(Wc_w + d * ND);
        float4 wa = wr[lane], wb = wr[lane + 32];
        float p = wa.x*ma.x + wa.y*ma.y + wa.z*ma.z + wa.w*ma.w
                + wb.x*mb.x + wb.y*mb.y + wb.z*mb.z + wb.w*mb.w;
        #pragma unroll
        for (int o = 16; o > 0; o >>= 1)
            p += __shfl_xor_sync(0xffffffffu, p, o);
        if (lane == 0) out_ctx[b * ND + d] = p + Wc_b[d];
    }

    // normalize this batch's alpha: 2048 float4, 8 per thread
    float4* a4 = (float4*)(alpha + (size_t)b * NS);
    float4 ev[8];
    #pragma unroll
    for (int k = 0; k < 8; k++) ev[k] = a4[k * 256 + t];
    #pragma unroll
    for (int k = 0; k < 8; k++) {
        int pos = (k * 256 + t) * 4;
        float4 o;
        if (len > 0 && pos >= len) {
            o = make_float4(0.f, 0.f, 0.f, 0.f);
        } else {
            o.x = (len > 0 && pos + 0 >= len) ? 0.f : __expf(ev[k].x - off) * Rinv;
            o.y = (len > 0 && pos + 1 >= len) ? 0.f : __expf(ev[k].y - off) * Rinv;
            o.z = (len > 0 && pos + 2 >= len) ? 0.f : __expf(ev[k].z - off) * Rinv;
            o.w = (len > 0 && pos + 3 >= len) ? 0.f : __expf(ev[k].w - off) * Rinv;
        }
        a4[k * 256 + t] = o;
    }
}

// ---------------- launch ----------------
extern "C" void kernel_launch(void* const* d_in, const int* in_sizes, int n_in,
                              void* d_out, int out_size) {
    const float* hs   = (const float*)d_in[0];  // [B,S,256]
    const float* ht   = (const float*)d_in[1];  // [B,256]
    const int*   slen = (const int*)  d_in[2];  // [B]
    const float* Wa_w = (const float*)d_in[3];  // [256,256]
    const float* Wa_b = (const float*)d_in[4];  // [256]
    const float* Wc_w = (const float*)d_in[5];  // [256,256]
    const float* Wc_b = (const float*)d_in[6];  // [256]

    float* alpha = (float*)d_out;                    // [B,S]
    float* ctx   = (float*)d_out + (size_t)NB * NS;  // [B,256]

    dim3 grid1(NPRE, NB);
    k_pre<<<grid1, 256>>>(ht, Wa_w, Wa_b);
    k_pre2<<<NB, 256>>>();
    dim3 grid2(NCHUNK, NB);
    k_main<<<grid2, 256>>>(hs, slen, alpha);
    k_fin<<<NB, 256>>>(Wc_w, Wc_b, slen, alpha, ctx);
}

// round 15
// speedup vs baseline: 1.1235x; 1.1235x over previous
#include <cuda_runtime.h>
#include <math.h>
#include <stdint.h>

#define NB 32
#define NS 8192
#define ND 256
#define NCHUNK 64          // blocks per batch in main pass
#define POS_PER_BLOCK 128  // rows per block
#define TILE_ROWS 16       // rows per cp.async tile
#define NTILES (POS_PER_BLOCK / TILE_ROWS)   // 8
#define NSTAGE 3
#define TILE_BYTES (TILE_ROWS * ND * 4)      // 16384
#define NPRE 16            // k_pre reduction split
#define EXP_OFF 48.0f      // fixed softmax offset (energies << 48+88)

// ---------------- scratch (no allocation allowed) ----------------
__device__ float g_V[NB * ND];             // v[b], accumulated by k_pre atomics,
                                           // reset to 0 by k_fin each run
__device__ float g_c0[NB];                 // ht[b] . Wa_b
__device__ float g_PL[NB * NCHUNK];        // per-block partial sum (fixed offset)
__device__ float g_PA[NB * NCHUNK * ND];   // per-block partial weighted row-sum

// ---------------- cp.async helpers ----------------
__device__ __forceinline__ void cp16(uint32_t dst, const void* src) {
    asm volatile("cp.async.cg.shared.global [%0], [%1], 16;\n" :: "r"(dst), "l"(src));
}
__device__ __forceinline__ void cp_commit() {
    asm volatile("cp.async.commit_group;\n" ::: "memory");
}
template <int N>
__device__ __forceinline__ void cp_wait() {
    asm volatile("cp.async.wait_group %0;\n" :: "n"(N) : "memory");
}

// ---------------- K1: v[b] += partial (16-way split over d), c0[b] -------
// g_V starts zero (static init on first run; k_fin resets it every run).
__global__ void __launch_bounds__(256)
k_pre(const float* __restrict__ ht,
      const float* __restrict__ Wa_w,
      const float* __restrict__ Wa_b) {
    int g = blockIdx.x, b = blockIdx.y, t = threadIdx.x;
    __shared__ float sh[16];
    if (t < 16) sh[t] = ht[b * ND + g * 16 + t];
    __syncthreads();
    const float* Wp = Wa_w + (size_t)(g * 16) * ND + t;
    float acc = 0.f;
    #pragma unroll
    for (int d = 0; d < 16; d++)                      // 16 loads, all in flight
        acc = fmaf(sh[d], Wp[(size_t)d * ND], acc);
    atomicAdd(&g_V[b * ND + t], acc);                 // RED, no return needed

    if (g == 0) {   // c0 = ht . Wa_b
        __shared__ float red[ND];
        red[t] = ht[b * ND + t] * Wa_b[t];
        __syncthreads();
        for (int s = 128; s > 0; s >>= 1) {
            if (t < s) red[t] += red[t + s];
            __syncthreads();
        }
        if (t == 0) g_c0[b] = red[0];
    }
}

// ---------------- K2: 3-buffer cp.async pipeline, 2 tiles in flight ------
// Per iter t: issue t+2 into slot (t+2)%3 FIRST (keeps 2 tiles landing),
// wait so tile t is resident, barrier, compute slot t%3, barrier (protects
// slot (t%3) from being overwritten by iter t+1's issue into (t+3)%3==t%3).
__global__ void __launch_bounds__(256, 4)
k_main(const float* __restrict__ hs, const int* __restrict__ slen,
       float* __restrict__ alpha) {
    __shared__ __align__(16) float sbuf[NSTAGE][TILE_ROWS * ND];  // 48KB

    int chunk = blockIdx.x, b = blockIdx.y;
    int tid = threadIdx.x, w = tid >> 5, lane = tid & 31;
    int len = slen[b];
    int len_eff = (len == 0) ? NS : len;
    float off = (len == 0) ? -10000.f : EXP_OFF;

    if (chunk * POS_PER_BLOCK >= len_eff) return;

    const float* gsrc = hs + ((size_t)b * NS + chunk * POS_PER_BLOCK) * ND;
    uint32_t sb = (uint32_t)__cvta_generic_to_shared(&sbuf[0][0]);

    // stage tiles 0 and 1 (slots 0, 1)
    #pragma unroll
    for (int tt = 0; tt < 2; tt++) {
        uint32_t dst = sb + tt * TILE_BYTES;
        const char* src = (const char*)(gsrc + tt * TILE_ROWS * ND);
        #pragma unroll
        for (int k = 0; k < 4; k++)
            cp16(dst + (tid + k * 256) * 16, src + (size_t)(tid + k * 256) * 16);
        cp_commit();
    }

    // v fragments: 2 loads from g_V (L2-hot)
    float c0 = g_c0[b];
    const float4* v4 = (const float4*)(g_V + b * ND);
    float4 va = v4[lane], vb = v4[lane + 32];

    float Lsum = 0.f;
    float4 Aa = make_float4(0.f, 0.f, 0.f, 0.f);
    float4 Ab = make_float4(0.f, 0.f, 0.f, 0.f);
    int s0 = chunk * POS_PER_BLOCK;

    #pragma unroll 1
    for (int t = 0; t < NTILES; t++) {
        if (t + 2 < NTILES) {            // issue tile t+2 BEFORE waiting
            uint32_t dst = sb + ((t + 2) % NSTAGE) * TILE_BYTES;
            const char* src = (const char*)(gsrc + (t + 2) * TILE_ROWS * ND);
            #pragma unroll
            for (int k = 0; k < 4; k++)
                cp16(dst + (tid + k * 256) * 16, src + (size_t)(tid + k * 256) * 16);
            cp_commit();
        }
        if (t + 2 < NTILES)      cp_wait<2>();   // tiles t+1, t+2 may pend
        else if (t + 1 < NTILES) cp_wait<1>();   // tile t+1 may pend
        else                     cp_wait<0>();
        __syncthreads();                 // tile t visible to all warps

        // compute: warp w handles rows 2w, 2w+1 of tile t (slot t%3)
        const float* sp = sbuf[t % NSTAGE] + (2 * w) * ND;
        float4 r1a = ((const float4*)sp)[lane];
        float4 r1b = ((const float4*)sp)[lane + 32];
        float4 r2a = ((const float4*)sp)[64 + lane];
        float4 r2b = ((const float4*)sp)[64 + lane + 32];

        float p1 = r1a.x*va.x + r1a.y*va.y + r1a.z*va.z + r1a.w*va.w
                 + r1b.x*vb.x + r1b.y*vb.y + r1b.z*vb.z + r1b.w*vb.w;
        float p2 = r2a.x*va.x + r2a.y*va.y + r2a.z*va.z + r2a.w*va.w
                 + r2b.x*vb.x + r2b.y*vb.y + r2b.z*vb.z + r2b.w*vb.w;
        #pragma unroll
        for (int o = 16; o > 0; o >>= 1) {
            p1 += __shfl_xor_sync(0xffffffffu, p1, o);
            p2 += __shfl_xor_sync(0xffffffffu, p2, o);
        }
        int s = s0 + t * TILE_ROWS + 2 * w;
        float e1 = p1 + c0, e2 = p2 + c0;
        e1 = (e1 > 0.f) ? e1 : 0.2f * e1;            // leaky relu
        e2 = (e2 > 0.f) ? e2 : 0.2f * e2;
        if (s + 0 >= len) e1 = -10000.f;             // length mask
        if (s + 1 >= len) e2 = -10000.f;
        if (lane == 0)
            *(float2*)(alpha + (size_t)b * NS + s) = make_float2(e1, e2);

        float q1 = __expf(e1 - off);                 // fixed offset softmax
        float q2 = __expf(e2 - off);
        Lsum += q1 + q2;
        Aa.x = fmaf(q2, r2a.x, fmaf(q1, r1a.x, Aa.x));
        Aa.y = fmaf(q2, r2a.y, fmaf(q1, r1a.y, Aa.y));
        Aa.z = fmaf(q2, r2a.z, fmaf(q1, r1a.z, Aa.z));
        Aa.w = fmaf(q2, r2a.w, fmaf(q1, r1a.w, Aa.w));
        Ab.x = fmaf(q2, r2b.x, fmaf(q1, r1b.x, Ab.x));
        Ab.y = fmaf(q2, r2b.y, fmaf(q1, r1b.y, Ab.y));
        Ab.z = fmaf(q2, r2b.z, fmaf(q1, r1b.z, Ab.z));
        Ab.w = fmaf(q2, r2b.w, fmaf(q1, r1b.w, Ab.w));
        __syncthreads();                 // protect slot t%3 from next issue
    }

    // combine 8 warps (sA/sL overlaid onto sbuf[0]; all reads barrier-protected)
    float* sA  = &sbuf[0][0];        // 8 x 256
    float* sLp = sA + 8 * ND;        // 8 floats (buffer holds 4096 floats)
    float* arow = sA + w * ND;
    arow[lane * 4 + 0] = Aa.x; arow[lane * 4 + 1] = Aa.y;
    arow[lane * 4 + 2] = Aa.z; arow[lane * 4 + 3] = Aa.w;
    arow[128 + lane * 4 + 0] = Ab.x; arow[128 + lane * 4 + 1] = Ab.y;
    arow[128 + lane * 4 + 2] = Ab.z; arow[128 + lane * 4 + 3] = Ab.w;
    if (lane == 0) sLp[w] = Lsum;
    __syncthreads();

    float acc = 0.f;
    #pragma unroll
    for (int j = 0; j < 8; j++) acc += sA[j * ND + tid];
    int pid = b * NCHUNK + chunk;
    g_PA[pid * ND + tid] = acc;
    if (tid == 0) {
        float lb = 0.f;
        #pragma unroll
        for (int j = 0; j < 8; j++) lb += sLp[j];
        g_PL[pid] = lb;
    }
}

// ---------------- K3: combine + context GEMV + alpha normalize (R11) -----
__global__ void __launch_bounds__(256)
k_fin(const float* __restrict__ Wc_w, const float* __restrict__ Wc_b,
      const int* __restrict__ slen, float* __restrict__ alpha,
      float* __restrict__ out_ctx) {
    int b = blockIdx.x, t = threadIdx.x, w = t >> 5, lane = t & 31;
    int len = slen[b];
    int len_eff = (len == 0) ? NS : len;
    float off = (len == 0) ? -10000.f : EXP_OFF;
    int nval = (len_eff + POS_PER_BLOCK - 1) / POS_PER_BLOCK;

    __shared__ float sLs[NCHUNK];
    __shared__ __align__(16) float sm[ND];
    if (t < NCHUNK) sLs[t] = (t < nval) ? g_PL[b * NCHUNK + t] : 0.f;
    __syncthreads();
    float Lg = 0.f;
    #pragma unroll 8
    for (int j = 0; j < NCHUNK; j++) Lg += sLs[j];
    float m = 0.f;
    #pragma unroll 8
    for (int j = 0; j < nval; j++)
        m += g_PA[(b * NCHUNK + j) * ND + t];
    float Rinv = 1.f / Lg;
    m *= Rinv;
    sm[t] = m;

    g_V[b * ND + t] = 0.f;        // reset accumulator for next graph replay
    __syncthreads();

    // context GEMV: warp per output row
    const float4* m4 = (const float4*)sm;
    float4 ma = m4[lane], mb = m4[lane + 32];
    #pragma unroll
    for (int d = w; d < ND; d += 8) {
        const float4* wr = (const float4*)(Wc_w + d * ND);
        float4 wa = wr[lane], wb = wr[lane + 32];
        float p = wa.x*ma.x + wa.y*ma.y + wa.z*ma.z + wa.w*ma.w
                + wb.x*mb.x + wb.y*mb.y + wb.z*mb.z + wb.w*mb.w;
        #pragma unroll
        for (int o = 16; o > 0; o >>= 1)
            p += __shfl_xor_sync(0xffffffffu, p, o);
        if (lane == 0) out_ctx[b * ND + d] = p + Wc_b[d];
    }

    // normalize this batch's alpha: 2048 float4, 8 per thread
    float4* a4 = (float4*)(alpha + (size_t)b * NS);
    float4 ev[8];
    #pragma unroll
    for (int k = 0; k < 8; k++) ev[k] = a4[k * 256 + t];
    #pragma unroll
    for (int k = 0; k < 8; k++) {
        int pos = (k * 256 + t) * 4;
        float4 o;
        if (len > 0 && pos >= len) {
            o = make_float4(0.f, 0.f, 0.f, 0.f);
        } else {
            o.x = (len > 0 && pos + 0 >= len) ? 0.f : __expf(ev[k].x - off) * Rinv;
            o.y = (len > 0 && pos + 1 >= len) ? 0.f : __expf(ev[k].y - off) * Rinv;
            o.z = (len > 0 && pos + 2 >= len) ? 0.f : __expf(ev[k].z - off) * Rinv;
            o.w = (len > 0 && pos + 3 >= len) ? 0.f : __expf(ev[k].w - off) * Rinv;
        }
        a4[k * 256 + t] = o;
    }
}

// ---------------- launch ----------------
extern "C" void kernel_launch(void* const* d_in, const int* in_sizes, int n_in,
                              void* d_out, int out_size) {
    const float* hs   = (const float*)d_in[0];  // [B,S,256]
    const float* ht   = (const float*)d_in[1];  // [B,256]
    const int*   slen = (const int*)  d_in[2];  // [B]
    const float* Wa_w = (const float*)d_in[3];  // [256,256]
    const float* Wa_b = (const float*)d_in[4];  // [256]
    const float* Wc_w = (const float*)d_in[5];  // [256,256]
    const float* Wc_b = (const float*)d_in[6];  // [256]

    float* alpha = (float*)d_out;                    // [B,S]
    float* ctx   = (float*)d_out + (size_t)NB * NS;  // [B,256]

    dim3 grid1(NPRE, NB);
    k_pre<<<grid1, 256>>>(ht, Wa_w, Wa_b);
    dim3 grid2(NCHUNK, NB);
    k_main<<<grid2, 256>>>(hs, slen, alpha);
    k_fin<<<NB, 256>>>(Wc_w, Wc_b, slen, alpha, ctx);
}

// round 16
// speedup vs baseline: 1.1285x; 1.0045x over previous
#include <cuda_runtime.h>
#include <math.h>
#include <stdint.h>

#define NB 32
#define NS 8192
#define ND 256
#define NCHUNK 64          // blocks per batch in main pass
#define POS_PER_BLOCK 128  // rows per block
#define TILE_ROWS 16       // rows per tile
#define NTILES (POS_PER_BLOCK / TILE_ROWS)   // 8
#define NSTAGE 3
#define TILE_BYTES (TILE_ROWS * ND * 4)      // 16384
#define NPRE 16            // k_pre reduction split
#define EXP_OFF 48.0f      // fixed softmax offset (energies << 48+88)

// ---------------- scratch (no allocation allowed) ----------------
__device__ float g_V[NB * ND];             // v[b], accumulated by k_pre atomics,
                                           // reset to 0 by k_fin each run
__device__ float g_c0[NB];                 // ht[b] . Wa_b
__device__ float g_PL[NB * NCHUNK];        // per-block partial sum (fixed offset)
__device__ float g_PA[NB * NCHUNK * ND];   // per-block partial weighted row-sum

// ---------------- TMA bulk + mbarrier helpers ----------------
__device__ __forceinline__ void mbar_init(uint32_t mbar, uint32_t cnt) {
    asm volatile("mbarrier.init.shared.b64 [%0], %1;" :: "r"(mbar), "r"(cnt) : "memory");
}
__device__ __forceinline__ void mbar_expect_tx(uint32_t mbar, uint32_t bytes) {
    asm volatile("mbarrier.arrive.expect_tx.shared.b64 _, [%0], %1;"
                 :: "r"(mbar), "r"(bytes) : "memory");
}
__device__ __forceinline__ void mbar_wait(uint32_t mbar, uint32_t parity) {
    asm volatile(
        "{\n\t.reg .pred P;\n"
        "W%=:\n\t"
        "mbarrier.try_wait.parity.acquire.cta.shared::cta.b64 P, [%0], %1, 0x989680;\n\t"
        "@!P bra W%=;\n\t}"
        :: "r"(mbar), "r"(parity) : "memory");
}
__device__ __forceinline__ void bulk_g2s(uint32_t dst, const void* src,
                                         uint32_t bytes, uint32_t mbar) {
    asm volatile(
        "cp.async.bulk.shared::cta.global.mbarrier::complete_tx::bytes "
        "[%0], [%1], %2, [%3];"
        :: "r"(dst), "l"(src), "r"(bytes), "r"(mbar) : "memory");
}

// ---------------- K1: v[b] += partial (16-way split over d), c0[b] -------
__global__ void __launch_bounds__(256)
k_pre(const float* __restrict__ ht,
      const float* __restrict__ Wa_w,
      const float* __restrict__ Wa_b) {
    int g = blockIdx.x, b = blockIdx.y, t = threadIdx.x;
    __shared__ float sh[16];
    if (t < 16) sh[t] = ht[b * ND + g * 16 + t];
    __syncthreads();
    const float* Wp = Wa_w + (size_t)(g * 16) * ND + t;
    float acc = 0.f;
    #pragma unroll
    for (int d = 0; d < 16; d++)                      // 16 loads, all in flight
        acc = fmaf(sh[d], Wp[(size_t)d * ND], acc);
    atomicAdd(&g_V[b * ND + t], acc);                 // RED, no return needed

    if (g == 0) {   // c0 = ht . Wa_b
        __shared__ float red[ND];
        red[t] = ht[b * ND + t] * Wa_b[t];
        __syncthreads();
        for (int s = 128; s > 0; s >>= 1) {
            if (t < s) red[t] += red[t + s];
            __syncthreads();
        }
        if (t == 0) g_c0[b] = red[0];
    }
}

// ---------------- K2: TMA-bulk 3-slot pipeline ----------------------------
// One cp.async.bulk (16KB) per tile, issued by thread 0; mbarrier parity
// wait per tile. Slot (t+2)%3 reuse is protected by the end-of-iter barrier
// of iteration t-1 (same invariant as the cp.async version).
__global__ void __launch_bounds__(256, 4)
k_main(const float* __restrict__ hs, const int* __restrict__ slen,
       float* __restrict__ alpha) {
    __shared__ __align__(128) float sbuf[NSTAGE][TILE_ROWS * ND];  // 48KB
    __shared__ __align__(8) unsigned long long mbar[NSTAGE];

    int chunk = blockIdx.x, b = blockIdx.y;
    int tid = threadIdx.x, w = tid >> 5, lane = tid & 31;
    int len = slen[b];
    int len_eff = (len == 0) ? NS : len;
    float off = (len == 0) ? -10000.f : EXP_OFF;

    if (chunk * POS_PER_BLOCK >= len_eff) return;

    const float* gsrc = hs + ((size_t)b * NS + chunk * POS_PER_BLOCK) * ND;
    uint32_t sb = (uint32_t)__cvta_generic_to_shared(&sbuf[0][0]);
    uint32_t mb = (uint32_t)__cvta_generic_to_shared(&mbar[0]);

    if (tid == 0) {
        #pragma unroll
        for (int s = 0; s < NSTAGE; s++) mbar_init(mb + s * 8, 1);
    }
    __syncthreads();                      // mbarriers visible

    if (tid == 0) {                       // stage tiles 0 and 1
        #pragma unroll
        for (int tt = 0; tt < 2; tt++) {
            mbar_expect_tx(mb + tt * 8, TILE_BYTES);
            bulk_g2s(sb + tt * TILE_BYTES, gsrc + tt * TILE_ROWS * ND,
                     TILE_BYTES, mb + tt * 8);
        }
    }

    // v fragments: 2 loads from g_V (L2-hot), overlapped with tile 0 landing
    float c0 = g_c0[b];
    const float4* v4 = (const float4*)(g_V + b * ND);
    float4 va = v4[lane], vb = v4[lane + 32];

    float Lsum = 0.f;
    float4 Aa = make_float4(0.f, 0.f, 0.f, 0.f);
    float4 Ab = make_float4(0.f, 0.f, 0.f, 0.f);
    int s0 = chunk * POS_PER_BLOCK;

    #pragma unroll
    for (int t = 0; t < NTILES; t++) {
        if (t + 2 < NTILES && tid == 0) { // issue tile t+2 into slot (t+2)%3
            int slot = (t + 2) % NSTAGE;
            mbar_expect_tx(mb + slot * 8, TILE_BYTES);
            bulk_g2s(sb + slot * TILE_BYTES, gsrc + (t + 2) * TILE_ROWS * ND,
                     TILE_BYTES, mb + slot * 8);
        }
        // wait for tile t (slot t%3, phase (t/3)&1 — constant after unroll)
        mbar_wait(mb + (t % NSTAGE) * 8, (t / NSTAGE) & 1);

        // compute: warp w handles rows 2w, 2w+1 of tile t
        const float* sp = sbuf[t % NSTAGE] + (2 * w) * ND;
        float4 r1a = ((const float4*)sp)[lane];
        float4 r1b = ((const float4*)sp)[lane + 32];
        float4 r2a = ((const float4*)sp)[64 + lane];
        float4 r2b = ((const float4*)sp)[64 + lane + 32];

        float p1 = r1a.x*va.x + r1a.y*va.y + r1a.z*va.z + r1a.w*va.w
                 + r1b.x*vb.x + r1b.y*vb.y + r1b.z*vb.z + r1b.w*vb.w;
        float p2 = r2a.x*va.x + r2a.y*va.y + r2a.z*va.z + r2a.w*va.w
                 + r2b.x*vb.x + r2b.y*vb.y + r2b.z*vb.z + r2b.w*vb.w;
        #pragma unroll
        for (int o = 16; o > 0; o >>= 1) {
            p1 += __shfl_xor_sync(0xffffffffu, p1, o);
            p2 += __shfl_xor_sync(0xffffffffu, p2, o);
        }
        int s = s0 + t * TILE_ROWS + 2 * w;
        float e1 = p1 + c0, e2 = p2 + c0;
        e1 = (e1 > 0.f) ? e1 : 0.2f * e1;            // leaky relu
        e2 = (e2 > 0.f) ? e2 : 0.2f * e2;
        if (s + 0 >= len) e1 = -10000.f;             // length mask
        if (s + 1 >= len) e2 = -10000.f;
        if (lane == 0)
            *(float2*)(alpha + (size_t)b * NS + s) = make_float2(e1, e2);

        float q1 = __expf(e1 - off);                 // fixed offset softmax
        float q2 = __expf(e2 - off);
        Lsum += q1 + q2;
        Aa.x = fmaf(q2, r2a.x, fmaf(q1, r1a.x, Aa.x));
        Aa.y = fmaf(q2, r2a.y, fmaf(q1, r1a.y, Aa.y));
        Aa.z = fmaf(q2, r2a.z, fmaf(q1, r1a.z, Aa.z));
        Aa.w = fmaf(q2, r2a.w, fmaf(q1, r1a.w, Aa.w));
        Ab.x = fmaf(q2, r2b.x, fmaf(q1, r1b.x, Ab.x));
        Ab.y = fmaf(q2, r2b.y, fmaf(q1, r1b.y, Ab.y));
        Ab.z = fmaf(q2, r2b.z, fmaf(q1, r1b.z, Ab.z));
        Ab.w = fmaf(q2, r2b.w, fmaf(q1, r1b.w, Ab.w));
        __syncthreads();                 // all reads of slot t%3 done -> safe
    }

    // combine 8 warps (sA/sL overlaid onto sbuf[0]; reads barrier-protected)
    float* sA  = &sbuf[0][0];        // 8 x 256
    float* sLp = sA + 8 * ND;        // 8 floats (buffer holds 4096 floats)
    float* arow = sA + w * ND;
    arow[lane * 4 + 0] = Aa.x; arow[lane * 4 + 1] = Aa.y;
    arow[lane * 4 + 2] = Aa.z; arow[lane * 4 + 3] = Aa.w;
    arow[128 + lane * 4 + 0] = Ab.x; arow[128 + lane * 4 + 1] = Ab.y;
    arow[128 + lane * 4 + 2] = Ab.z; arow[128 + lane * 4 + 3] = Ab.w;
    if (lane == 0) sLp[w] = Lsum;
    __syncthreads();

    float acc = 0.f;
    #pragma unroll
    for (int j = 0; j < 8; j++) acc += sA[j * ND + tid];
    int pid = b * NCHUNK + chunk;
    g_PA[pid * ND + tid] = acc;
    if (tid == 0) {
        float lb = 0.f;
        #pragma unroll
        for (int j = 0; j < 8; j++) lb += sLp[j];
        g_PL[pid] = lb;
    }
}

// ---------------- K3: combine + context GEMV + alpha normalize -----------
__global__ void __launch_bounds__(256)
k_fin(const float* __restrict__ Wc_w, const float* __restrict__ Wc_b,
      const int* __restrict__ slen, float* __restrict__ alpha,
      float* __restrict__ out_ctx) {
    int b = blockIdx.x, t = threadIdx.x, w = t >> 5, lane = t & 31;
    int len = slen[b];
    int len_eff = (len == 0) ? NS : len;
    float off = (len == 0) ? -10000.f : EXP_OFF;
    int nval = (len_eff + POS_PER_BLOCK - 1) / POS_PER_BLOCK;

    __shared__ float sLs[NCHUNK];
    __shared__ __align__(16) float sm[ND];
    if (t < NCHUNK) sLs[t] = (t < nval) ? g_PL[b * NCHUNK + t] : 0.f;
    __syncthreads();
    float Lg = 0.f;
    #pragma unroll 8
    for (int j = 0; j < NCHUNK; j++) Lg += sLs[j];
    float m = 0.f;
    #pragma unroll 8
    for (int j = 0; j < nval; j++)
        m += g_PA[(b * NCHUNK + j) * ND + t];
    float Rinv = 1.f / Lg;
    m *= Rinv;
    sm[t] = m;

    g_V[b * ND + t] = 0.f;        // reset accumulator for next graph replay
    __syncthreads();

    // context GEMV: warp per output row
    const float4* m4 = (const float4*)sm;
    float4 ma = m4[lane], mb = m4[lane + 32];
    #pragma unroll
    for (int d = w; d < ND; d += 8) {
        const float4* wr = (const float4*)(Wc_w + d * ND);
        float4 wa = wr[lane], wb = wr[lane + 32];
        float p = wa.x*ma.x + wa.y*ma.y + wa.z*ma.z + wa.w*ma.w
                + wb.x*mb.x + wb.y*mb.y + wb.z*mb.z + wb.w*mb.w;
        #pragma unroll
        for (int o = 16; o > 0; o >>= 1)
            p += __shfl_xor_sync(0xffffffffu, p, o);
        if (lane == 0) out_ctx[b * ND + d] = p + Wc_b[d];
    }

    // normalize this batch's alpha: 2048 float4, 8 per thread
    float4* a4 = (float4*)(alpha + (size_t)b * NS);
    float4 ev[8];
    #pragma unroll
    for (int k = 0; k < 8; k++) ev[k] = a4[k * 256 + t];
    #pragma unroll
    for (int k = 0; k < 8; k++) {
        int pos = (k * 256 + t) * 4;
        float4 o;
        if (len > 0 && pos >= len) {
            o = make_float4(0.f, 0.f, 0.f, 0.f);
        } else {
            o.x = (len > 0 && pos + 0 >= len) ? 0.f : __expf(ev[k].x - off) * Rinv;
            o.y = (len > 0 && pos + 1 >= len) ? 0.f : __expf(ev[k].y - off) * Rinv;
            o.z = (len > 0 && pos + 2 >= len) ? 0.f : __expf(ev[k].z - off) * Rinv;
            o.w = (len > 0 && pos + 3 >= len) ? 0.f : __expf(ev[k].w - off) * Rinv;
        }
        a4[k * 256 + t] = o;
    }
}

// ---------------- launch ----------------
extern "C" void kernel_launch(void* const* d_in, const int* in_sizes, int n_in,
                              void* d_out, int out_size) {
    const float* hs   = (const float*)d_in[0];  // [B,S,256]
    const float* ht   = (const float*)d_in[1];  // [B,256]
    const int*   slen = (const int*)  d_in[2];  // [B]
    const float* Wa_w = (const float*)d_in[3];  // [256,256]
    const float* Wa_b = (const float*)d_in[4];  // [256]
    const float* Wc_w = (const float*)d_in[5];  // [256,256]
    const float* Wc_b = (const float*)d_in[6];  // [256]

    float* alpha = (float*)d_out;                    // [B,S]
    float* ctx   = (float*)d_out + (size_t)NB * NS;  // [B,256]

    dim3 grid1(NPRE, NB);
    k_pre<<<grid1, 256>>>(ht, Wa_w, Wa_b);
    dim3 grid2(NCHUNK, NB);
    k_main<<<grid2, 256>>>(hs, slen, alpha);
    k_fin<<<NB, 256>>>(Wc_w, Wc_b, slen, alpha, ctx);
}

// round 17
// speedup vs baseline: 1.1658x; 1.0330x over previous
#include <cuda_runtime.h>
#include <math.h>
#include <stdint.h>

#define NB 32
#define NS 8192
#define ND 256
#define NCHUNK 64          // blocks per batch in main pass
#define POS_PER_BLOCK 128  // rows per block
#define TILE_ROWS 16       // rows per tile
#define NTILES (POS_PER_BLOCK / TILE_ROWS)   // 8
#define NSTAGE 3
#define TILE_BYTES (TILE_ROWS * ND * 4)      // 16384
#define NPRE 16            // k_pre reduction split
#define EXP_OFF 48.0f      // fixed softmax offset (energies << 48+88)

// ---------------- scratch (no allocation allowed) ----------------
__device__ float g_V[NB * ND];             // v[b], accumulated by k_pre atomics,
                                           // reset to 0 by k_fin each run
__device__ float g_c0[NB];                 // ht[b] . Wa_b
__device__ float g_PL[NB * NCHUNK];        // per-block partial sum (fixed offset)
__device__ float g_PA[NB * NCHUNK * ND];   // per-block partial weighted row-sum

// ---------------- TMA bulk + mbarrier helpers ----------------
__device__ __forceinline__ void mbar_init(uint32_t mbar, uint32_t cnt) {
    asm volatile("mbarrier.init.shared.b64 [%0], %1;" :: "r"(mbar), "r"(cnt) : "memory");
}
__device__ __forceinline__ void mbar_expect_tx(uint32_t mbar, uint32_t bytes) {
    asm volatile("mbarrier.arrive.expect_tx.shared.b64 _, [%0], %1;"
                 :: "r"(mbar), "r"(bytes) : "memory");
}
__device__ __forceinline__ void mbar_wait(uint32_t mbar, uint32_t parity) {
    asm volatile(
        "{\n\t.reg .pred P;\n"
        "W%=:\n\t"
        "mbarrier.try_wait.parity.acquire.cta.shared::cta.b64 P, [%0], %1, 0x989680;\n\t"
        "@!P bra W%=;\n\t}"
        :: "r"(mbar), "r"(parity) : "memory");
}
__device__ __forceinline__ void bulk_g2s(uint32_t dst, const void* src,
                                         uint32_t bytes, uint32_t mbar) {
    asm volatile(
        "cp.async.bulk.shared::cta.global.mbarrier::complete_tx::bytes "
        "[%0], [%1], %2, [%3];"
        :: "r"(dst), "l"(src), "r"(bytes), "r"(mbar) : "memory");
}

// ---------------- K1: v[b] += partial (16-way split over d), c0[b] -------
__global__ void __launch_bounds__(256)
k_pre(const float* __restrict__ ht,
      const float* __restrict__ Wa_w,
      const float* __restrict__ Wa_b) {
    int g = blockIdx.x, b = blockIdx.y, t = threadIdx.x;
    __shared__ float sh[16];
    if (t < 16) sh[t] = ht[b * ND + g * 16 + t];
    __syncthreads();
    const float* Wp = Wa_w + (size_t)(g * 16) * ND + t;
    float acc = 0.f;
    #pragma unroll
    for (int d = 0; d < 16; d++)                      // 16 loads, all in flight
        acc = fmaf(sh[d], Wp[(size_t)d * ND], acc);
    atomicAdd(&g_V[b * ND + t], acc);                 // RED, no return needed

    if (g == 0) {   // c0 = ht . Wa_b
        __shared__ float red[ND];
        red[t] = ht[b * ND + t] * Wa_b[t];
        __syncthreads();
        for (int s = 128; s > 0; s >>= 1) {
            if (t < s) red[t] += red[t + s];
            __syncthreads();
        }
        if (t == 0) g_c0[b] = red[0];
    }
    cudaTriggerProgrammaticLaunchCompletion();        // outputs done -> fire PDL
}

// ---------------- K2: TMA-bulk 3-slot pipeline + PDL ----------------------
__global__ void __launch_bounds__(256, 4)
k_main(const float* __restrict__ hs, const int* __restrict__ slen,
       float* __restrict__ alpha) {
    __shared__ __align__(128) float sbuf[NSTAGE][TILE_ROWS * ND];  // 48KB
    __shared__ __align__(8) unsigned long long mbar[NSTAGE];

    int chunk = blockIdx.x, b = blockIdx.y;
    int tid = threadIdx.x, w = tid >> 5, lane = tid & 31;
    int len = slen[b];                   // input: safe before griddepsync
    int len_eff = (len == 0) ? NS : len;
    float off = (len == 0) ? -10000.f : EXP_OFF;

    if (chunk * POS_PER_BLOCK >= len_eff) {
        cudaGridDependencySynchronize();  // must not skip the dependency
        return;
    }

    const float* gsrc = hs + ((size_t)b * NS + chunk * POS_PER_BLOCK) * ND;
    uint32_t sb = (uint32_t)__cvta_generic_to_shared(&sbuf[0][0]);
    uint32_t mb = (uint32_t)__cvta_generic_to_shared(&mbar[0]);

    if (tid == 0) {
        #pragma unroll
        for (int s = 0; s < NSTAGE; s++) mbar_init(mb + s * 8, 1);
    }
    __syncthreads();                      // mbarriers visible

    if (tid == 0) {                       // stage tiles 0 and 1 (hs = input)
        #pragma unroll
        for (int tt = 0; tt < 2; tt++) {
            mbar_expect_tx(mb + tt * 8, TILE_BYTES);
            bulk_g2s(sb + tt * TILE_BYTES, gsrc + tt * TILE_ROWS * ND,
                     TILE_BYTES, mb + tt * 8);
        }
    }

    // wait for k_pre's g_V/g_c0 — overlapped with TMA tile 0/1 in flight
    cudaGridDependencySynchronize();

    float c0 = g_c0[b];
    const float4* v4 = (const float4*)(g_V + b * ND);
    float4 va = v4[lane], vb = v4[lane + 32];

    float Lsum = 0.f;
    float4 Aa = make_float4(0.f, 0.f, 0.f, 0.f);
    float4 Ab = make_float4(0.f, 0.f, 0.f, 0.f);
    int s0 = chunk * POS_PER_BLOCK;

    #pragma unroll
    for (int t = 0; t < NTILES; t++) {
        if (t + 2 < NTILES && tid == 0) { // issue tile t+2 into slot (t+2)%3
            int slot = (t + 2) % NSTAGE;
            mbar_expect_tx(mb + slot * 8, TILE_BYTES);
            bulk_g2s(sb + slot * TILE_BYTES, gsrc + (t + 2) * TILE_ROWS * ND,
                     TILE_BYTES, mb + slot * 8);
        }
        mbar_wait(mb + (t % NSTAGE) * 8, (t / NSTAGE) & 1);

        // compute: warp w handles rows 2w, 2w+1 of tile t
        const float* sp = sbuf[t % NSTAGE] + (2 * w) * ND;
        float4 r1a = ((const float4*)sp)[lane];
        float4 r1b = ((const float4*)sp)[lane + 32];
        float4 r2a = ((const float4*)sp)[64 + lane];
        float4 r2b = ((const float4*)sp)[64 + lane + 32];

        float p1 = r1a.x*va.x + r1a.y*va.y + r1a.z*va.z + r1a.w*va.w
                 + r1b.x*vb.x + r1b.y*vb.y + r1b.z*vb.z + r1b.w*vb.w;
        float p2 = r2a.x*va.x + r2a.y*va.y + r2a.z*va.z + r2a.w*va.w
                 + r2b.x*vb.x + r2b.y*vb.y + r2b.z*vb.z + r2b.w*vb.w;
        #pragma unroll
        for (int o = 16; o > 0; o >>= 1) {
            p1 += __shfl_xor_sync(0xffffffffu, p1, o);
            p2 += __shfl_xor_sync(0xffffffffu, p2, o);
        }
        int s = s0 + t * TILE_ROWS + 2 * w;
        float e1 = p1 + c0, e2 = p2 + c0;
        e1 = (e1 > 0.f) ? e1 : 0.2f * e1;            // leaky relu
        e2 = (e2 > 0.f) ? e2 : 0.2f * e2;
        if (s + 0 >= len) e1 = -10000.f;             // length mask
        if (s + 1 >= len) e2 = -10000.f;
        if (lane == 0)
            *(float2*)(alpha + (size_t)b * NS + s) = make_float2(e1, e2);

        float q1 = __expf(e1 - off);                 // fixed offset softmax
        float q2 = __expf(e2 - off);
        Lsum += q1 + q2;
        Aa.x = fmaf(q2, r2a.x, fmaf(q1, r1a.x, Aa.x));
        Aa.y = fmaf(q2, r2a.y, fmaf(q1, r1a.y, Aa.y));
        Aa.z = fmaf(q2, r2a.z, fmaf(q1, r1a.z, Aa.z));
        Aa.w = fmaf(q2, r2a.w, fmaf(q1, r1a.w, Aa.w));
        Ab.x = fmaf(q2, r2b.x, fmaf(q1, r1b.x, Ab.x));
        Ab.y = fmaf(q2, r2b.y, fmaf(q1, r1b.y, Ab.y));
        Ab.z = fmaf(q2, r2b.z, fmaf(q1, r1b.z, Ab.z));
        Ab.w = fmaf(q2, r2b.w, fmaf(q1, r1b.w, Ab.w));
        __syncthreads();                 // all reads of slot t%3 done -> safe
    }

    // combine 8 warps (sA/sL overlaid onto sbuf[0]; reads barrier-protected)
    float* sA  = &sbuf[0][0];        // 8 x 256
    float* sLp = sA + 8 * ND;        // 8 floats (buffer holds 4096 floats)
    float* arow = sA + w * ND;
    arow[lane * 4 + 0] = Aa.x; arow[lane * 4 + 1] = Aa.y;
    arow[lane * 4 + 2] = Aa.z; arow[lane * 4 + 3] = Aa.w;
    arow[128 + lane * 4 + 0] = Ab.x; arow[128 + lane * 4 + 1] = Ab.y;
    arow[128 + lane * 4 + 2] = Ab.z; arow[128 + lane * 4 + 3] = Ab.w;
    if (lane == 0) sLp[w] = Lsum;
    __syncthreads();

    float acc = 0.f;
    #pragma unroll
    for (int j = 0; j < 8; j++) acc += sA[j * ND + tid];
    int pid = b * NCHUNK + chunk;
    g_PA[pid * ND + tid] = acc;
    if (tid == 0) {
        float lb = 0.f;
        #pragma unroll
        for (int j = 0; j < 8; j++) lb += sLp[j];
        g_PL[pid] = lb;
    }
}

// ---------------- K3: combine + context GEMV + alpha normalize + PDL -----
__global__ void __launch_bounds__(256)
k_fin(const float* __restrict__ Wc_w, const float* __restrict__ Wc_b,
      const int* __restrict__ slen, float* __restrict__ alpha,
      float* __restrict__ out_ctx) {
    int b = blockIdx.x, t = threadIdx.x, w = t >> 5, lane = t & 31;
    int len = slen[b];                   // input: safe pre-sync
    int len_eff = (len == 0) ? NS : len;
    float off = (len == 0) ? -10000.f : EXP_OFF;
    int nval = (len_eff + POS_PER_BLOCK - 1) / POS_PER_BLOCK;

    cudaGridDependencySynchronize();     // wait for k_main outputs

    __shared__ float sLs[NCHUNK];
    __shared__ __align__(16) float sm[ND];
    if (t < NCHUNK) sLs[t] = (t < nval) ? g_PL[b * NCHUNK + t] : 0.f;
    __syncthreads();
    float Lg = 0.f;
    #pragma unroll 8
    for (int j = 0; j < NCHUNK; j++) Lg += sLs[j];
    float m = 0.f;
    #pragma unroll 8
    for (int j = 0; j < nval; j++)
        m += g_PA[(b * NCHUNK + j) * ND + t];
    float Rinv = 1.f / Lg;
    m *= Rinv;
    sm[t] = m;

    g_V[b * ND + t] = 0.f;        // reset accumulator for next graph replay
    __syncthreads();

    // context GEMV: warp per output row
    const float4* m4 = (const float4*)sm;
    float4 ma = m4[lane], mb = m4[lane + 32];
    #pragma unroll
    for (int d = w; d < ND; d += 8) {
        const float4* wr = (const float4*)(Wc_w + d * ND);
        float4 wa = wr[lane], wb = wr[lane + 32];
        float p = wa.x*ma.x + wa.y*ma.y + wa.z*ma.z + wa.w*ma.w
                + wb.x*mb.x + wb.y*mb.y + wb.z*mb.z + wb.w*mb.w;
        #pragma unroll
        for (int o = 16; o > 0; o >>= 1)
            p += __shfl_xor_sync(0xffffffffu, p, o);
        if (lane == 0) out_ctx[b * ND + d] = p + Wc_b[d];
    }

    // normalize this batch's alpha: 2048 float4, 8 per thread
    float4* a4 = (float4*)(alpha + (size_t)b * NS);
    float4 ev[8];
    #pragma unroll
    for (int k = 0; k < 8; k++) ev[k] = a4[k * 256 + t];
    #pragma unroll
    for (int k = 0; k < 8; k++) {
        int pos = (k * 256 + t) * 4;
        float4 o;
        if (len > 0 && pos >= len) {
            o = make_float4(0.f, 0.f, 0.f, 0.f);
        } else {
            o.x = (len > 0 && pos + 0 >= len) ? 0.f : __expf(ev[k].x - off) * Rinv;
            o.y = (len > 0 && pos + 1 >= len) ? 0.f : __expf(ev[k].y - off) * Rinv;
            o.z = (len > 0 && pos + 2 >= len) ? 0.f : __expf(ev[k].z - off) * Rinv;
            o.w = (len > 0 && pos + 3 >= len) ? 0.f : __expf(ev[k].w - off) * Rinv;
        }
        a4[k * 256 + t] = o;
    }
}

// ---------------- launch (PDL chain) ----------------
extern "C" void kernel_launch(void* const* d_in, const int* in_sizes, int n_in,
                              void* d_out, int out_size) {
    const float* hs   = (const float*)d_in[0];  // [B,S,256]
    const float* ht   = (const float*)d_in[1];  // [B,256]
    const int*   slen = (const int*)  d_in[2];  // [B]
    const float* Wa_w = (const float*)d_in[3];  // [256,256]
    const float* Wa_b = (const float*)d_in[4];  // [256]
    const float* Wc_w = (const float*)d_in[5];  // [256,256]
    const float* Wc_b = (const float*)d_in[6];  // [256]

    float* alpha = (float*)d_out;                    // [B,S]
    float* ctx   = (float*)d_out + (size_t)NB * NS;  // [B,256]

    dim3 grid1(NPRE, NB);
    k_pre<<<grid1, 256>>>(ht, Wa_w, Wa_b);

    cudaLaunchAttribute attr[1];
    attr[0].id = cudaLaunchAttributeProgrammaticStreamSerialization;
    attr[0].val.programmaticStreamSerializationAllowed = 1;

    {   // k_main with PDL on k_pre
        cudaLaunchConfig_t cfg = {};
        cfg.gridDim = dim3(NCHUNK, NB, 1);
        cfg.blockDim = dim3(256, 1, 1);
        cfg.attrs = attr;
        cfg.numAttrs = 1;
        cudaLaunchKernelEx(&cfg, k_main, hs, slen, alpha);
    }
    {   // k_fin with PDL on k_main
        cudaLaunchConfig_t cfg = {};
        cfg.gridDim = dim3(NB, 1, 1);
        cfg.blockDim = dim3(256, 1, 1);
        cfg.attrs = attr;
        cfg.numAttrs = 1;
        cudaLaunchKernelEx(&cfg, k_fin, Wc_w, Wc_b, slen, alpha, ctx);
    }
}